// round 13
// baseline (speedup 1.0000x reference)
#include <cuda_runtime.h>
#include <cuda_bf16.h>
#include <cstdint>
#include <cstddef>

// Problem constants (B=4, T=2048, C=2048, H=16, D=128)
#define B_  4
#define T_  2048
#define C_  2048
#define H_  16
#define D_  128
#define M_  (B_ * T_)       // 8192
#define N1_ (3 * C_)        // 6144

// softmax scale * log2(e)  (folded into Q at QKV-GEMM epilogue)
#define SC_Q (0.08838834764831844f * 1.44269504088896340736f)

// ---------------------------------------------------------------------------
// Scratch (__device__ globals; no allocs allowed)
// ---------------------------------------------------------------------------
__device__ __nv_bfloat16 g_xhi[(size_t)M_ * C_];
__device__ __nv_bfloat16 g_xlo[(size_t)M_ * C_];
__device__ __nv_bfloat16 g_w1hi[(size_t)N1_ * C_];
__device__ __nv_bfloat16 g_w1lo[(size_t)N1_ * C_];
__device__ __nv_bfloat16 g_w2hi[(size_t)C_ * C_];
__device__ __nv_bfloat16 g_w2lo[(size_t)C_ * C_];
// head-major Q/K/V: [(b*H+h)*T + t]*D + d
__device__ __nv_bfloat16 g_qhi[(size_t)M_ * C_];
__device__ __nv_bfloat16 g_qlo[(size_t)M_ * C_];
__device__ __nv_bfloat16 g_khi[(size_t)M_ * C_];
__device__ __nv_bfloat16 g_klo[(size_t)M_ * C_];
__device__ __nv_bfloat16 g_vhi[(size_t)M_ * C_];
__device__ __nv_bfloat16 g_vlo[(size_t)M_ * C_];
// attention output (token-major [t, C]), feeds proj GEMM
__device__ __nv_bfloat16 g_ahi[(size_t)M_ * C_];
__device__ __nv_bfloat16 g_alo[(size_t)M_ * C_];

// ---------------------------------------------------------------------------
// Helpers
// ---------------------------------------------------------------------------
__device__ __forceinline__ uint32_t smem_u32(const void* p) {
    uint32_t a;
    asm("{ .reg .u64 t; cvta.to.shared.u64 t, %1; cvt.u32.u64 %0, t; }"
        : "=r"(a) : "l"(p));
    return a;
}

#define LDSM_X4(r, a)                                                          \
    asm volatile("ldmatrix.sync.aligned.m8n8.x4.shared.b16 {%0,%1,%2,%3}, [%4];" \
        : "=r"((r)[0]), "=r"((r)[1]), "=r"((r)[2]), "=r"((r)[3]) : "r"(a))

#define LDSM_X4_T(r, a)                                                        \
    asm volatile("ldmatrix.sync.aligned.m8n8.x4.trans.shared.b16 {%0,%1,%2,%3}, [%4];" \
        : "=r"((r)[0]), "=r"((r)[1]), "=r"((r)[2]), "=r"((r)[3]) : "r"(a))

#define MMA16816(c, a, b0v, b1v)                                               \
    asm volatile("mma.sync.aligned.m16n8k16.row.col.f32.bf16.bf16.f32 "        \
        "{%0,%1,%2,%3}, {%4,%5,%6,%7}, {%8,%9}, {%0,%1,%2,%3};"                \
        : "+f"((c)[0]), "+f"((c)[1]), "+f"((c)[2]), "+f"((c)[3])               \
        : "r"((a)[0]), "r"((a)[1]), "r"((a)[2]), "r"((a)[3]),                  \
          "r"(b0v), "r"(b1v))

#define CP_ASYNC16(dst, src)                                                   \
    asm volatile("cp.async.cg.shared.global [%0], [%1], 16;"                   \
        :: "r"(dst), "l"(src))
#define CP_COMMIT()  asm volatile("cp.async.commit_group;" ::: "memory")
#define CP_WAIT1()   asm volatile("cp.async.wait_group 1;" ::: "memory")
#define CP_WAIT0()   asm volatile("cp.async.wait_group 0;" ::: "memory")

__device__ __forceinline__ uint32_t pack_bf2(float a, float b) {
    __nv_bfloat162 t = __halves2bfloat162(__float2bfloat16_rn(a),
                                          __float2bfloat16_rn(b));
    return *(uint32_t*)&t;
}

__device__ __forceinline__ void split4(float4 v, uint32_t& h0, uint32_t& h1,
                                       uint32_t& l0, uint32_t& l1) {
    __nv_bfloat16 ax = __float2bfloat16_rn(v.x);
    __nv_bfloat16 ay = __float2bfloat16_rn(v.y);
    __nv_bfloat16 az = __float2bfloat16_rn(v.z);
    __nv_bfloat16 aw = __float2bfloat16_rn(v.w);
    __nv_bfloat162 th0 = __halves2bfloat162(ax, ay);
    __nv_bfloat162 th1 = __halves2bfloat162(az, aw);
    h0 = *(uint32_t*)&th0;
    h1 = *(uint32_t*)&th1;
    l0 = pack_bf2(v.x - __bfloat162float(ax), v.y - __bfloat162float(ay));
    l1 = pack_bf2(v.z - __bfloat162float(az), v.w - __bfloat162float(aw));
}

__device__ __forceinline__ void split2(float a, float b, uint32_t& h, uint32_t& l) {
    __nv_bfloat16 ha = __float2bfloat16_rn(a);
    __nv_bfloat16 hb = __float2bfloat16_rn(b);
    __nv_bfloat162 th = __halves2bfloat162(ha, hb);
    h = *(uint32_t*)&th;
    l = pack_bf2(a - __bfloat162float(ha), b - __bfloat162float(hb));
}

// ---------------------------------------------------------------------------
// Split fp32 -> bf16 hi/lo (for x)
// ---------------------------------------------------------------------------
__global__ void split_kernel(const float* __restrict__ in,
                             __nv_bfloat16* __restrict__ hi,
                             __nv_bfloat16* __restrict__ lo, int n4)
{
    int i = blockIdx.x * blockDim.x + threadIdx.x;
    if (i >= n4) return;
    float4 v = ((const float4*)in)[i];
    uint32_t h0, h1, l0, l1;
    split4(v, h0, h1, l0, l1);
    uint32_t* H = (uint32_t*)hi;
    uint32_t* L = (uint32_t*)lo;
    H[2 * i] = h0; H[2 * i + 1] = h1;
    L[2 * i] = l0; L[2 * i + 1] = l1;
}

// ---------------------------------------------------------------------------
// Split + transpose: W[K,N] fp32 -> W^T hi/lo bf16 [N,K]
// ---------------------------------------------------------------------------
__global__ __launch_bounds__(256)
void split_transpose_kernel(const float* __restrict__ W,
                            __nv_bfloat16* __restrict__ hiT,
                            __nv_bfloat16* __restrict__ loT, int K, int N)
{
    __shared__ float t[32][33];
    const int n0 = blockIdx.x * 32, k0 = blockIdx.y * 32;
    const int tx = threadIdx.x, ty = threadIdx.y;
#pragma unroll
    for (int j = 0; j < 4; j++)
        t[ty + j * 8][tx] = W[(size_t)(k0 + ty + j * 8) * N + n0 + tx];
    __syncthreads();
#pragma unroll
    for (int j = 0; j < 4; j++) {
        float v = t[tx][ty + j * 8];
        __nv_bfloat16 h = __float2bfloat16_rn(v);
        __nv_bfloat16 l = __float2bfloat16_rn(v - __bfloat162float(h));
        size_t o = (size_t)(n0 + ty + j * 8) * K + k0 + tx;
        hiT[o] = h;
        loT[o] = l;
    }
}

// ---------------------------------------------------------------------------
// mma.sync split-bf16 GEMM (exact R7 version: 2-stage, 2 CTAs/SM):
// CTA tile 128x128, 8 warps of 64x32, K-chunk 32, double-buffered.
// SMEM/stage: Ahi 8K | Alo 8K | Bhi 8K | Blo 8K = 32K; 2 stages = 64K/CTA.
// 64B rows, swizzle: (seg*16) ^ (((row>>1)&3)<<4)  -> conflict-free ldsm.
// MODE 0: fp32 out + bias (proj). MODE 1: QKV split-bf16 head-major epilogue.
// ---------------------------------------------------------------------------
#define GK_STAGE 32768u
#define GEMM_SMEM (2 * 32768)

#define SW64(row, segb) ((uint32_t)((row) * 64) + (((uint32_t)(segb)) ^ ((((uint32_t)(row) >> 1) & 3u) << 4)))

__device__ __forceinline__ void load_chunk32(uint32_t sb, int buf,
                                             const __nv_bfloat16* aHi,
                                             const __nv_bfloat16* aLo,
                                             const __nv_bfloat16* bHi,
                                             const __nv_bfloat16* bLo,
                                             int k0, int Kdim, int tid)
{
    const uint32_t st = sb + (uint32_t)buf * GK_STAGE;
    const __nv_bfloat16* srcs[4] = { aHi, aLo, bHi, bLo };
#pragma unroll
    for (int tl = 0; tl < 4; tl++) {
        const __nv_bfloat16* s = srcs[tl] + k0;
        const uint32_t tb = st + (uint32_t)tl * 8192u;
#pragma unroll
        for (int l = 0; l < 2; l++) {
            int idx = tid + l * 256;          // 512 slots: 128 rows x 4 segs
            int row = idx >> 2, seg = idx & 3;
            CP_ASYNC16(tb + SW64(row, seg * 16),
                       s + (size_t)row * Kdim + seg * 8);
        }
    }
    CP_COMMIT();
}

template <int MODE>
__global__ __launch_bounds__(256, 2)
void mma_gemm(const __nv_bfloat16* __restrict__ Ahi, const __nv_bfloat16* __restrict__ Alo,
              const __nv_bfloat16* __restrict__ Bhi, const __nv_bfloat16* __restrict__ Blo,
              const float* __restrict__ bias, float* __restrict__ Cm,
              __nv_bfloat16* __restrict__ qhi, __nv_bfloat16* __restrict__ qlo,
              __nv_bfloat16* __restrict__ khi, __nv_bfloat16* __restrict__ klo,
              __nv_bfloat16* __restrict__ vhi, __nv_bfloat16* __restrict__ vlo,
              int Ndim, int Kdim)
{
    extern __shared__ __align__(128) char smem[];
    const uint32_t sb = smem_u32(smem);
    const int tid  = threadIdx.x;
    const int wid  = tid >> 5;
    const int lane = tid & 31;
    const int wm   = wid & 1;        // 0..1 -> 64 rows
    const int wn   = wid >> 1;       // 0..3 -> 32 cols
    const int m0   = blockIdx.y * 128;
    const int n0   = blockIdx.x * 128;

    const __nv_bfloat16* aHi = Ahi + (size_t)m0 * Kdim;
    const __nv_bfloat16* aLo = Alo + (size_t)m0 * Kdim;
    const __nv_bfloat16* bHi = Bhi + (size_t)n0 * Kdim;
    const __nv_bfloat16* bLo = Blo + (size_t)n0 * Kdim;

    const int aRow = wm * 64 + (lane & 15);
    const uint32_t aKadd = (uint32_t)((lane >> 4) << 4);
    const int bRowB = wn * 32 + ((lane >> 4) & 1) * 8 + (lane & 7);
    const uint32_t bKadd = (uint32_t)(((lane >> 3) & 1) << 4);

    float c[4][4][4];
#pragma unroll
    for (int mi = 0; mi < 4; mi++)
#pragma unroll
        for (int ni = 0; ni < 4; ni++)
#pragma unroll
            for (int e = 0; e < 4; e++) c[mi][ni][e] = 0.f;

    const int nch = Kdim >> 5;       // K-chunks of 32
    load_chunk32(sb, 0, aHi, aLo, bHi, bLo, 0, Kdim, tid);

    for (int t = 0; t < nch; t++) {
        if (t + 1 < nch) {
            load_chunk32(sb, (t + 1) & 1, aHi, aLo, bHi, bLo, (t + 1) << 5, Kdim, tid);
            CP_WAIT1();
        } else {
            CP_WAIT0();
        }
        __syncthreads();

        const uint32_t st  = sb + (uint32_t)(t & 1) * GK_STAGE;
        const uint32_t tAh = st;
        const uint32_t tAl = st + 8192u;
        const uint32_t tBh = st + 16384u;
        const uint32_t tBl = st + 24576u;

#pragma unroll
        for (int ks = 0; ks < 2; ks++) {
            uint32_t bh4[2][4], bl4[2][4];
#pragma unroll
            for (int pr = 0; pr < 2; pr++) {
                const int br = bRowB + pr * 16;
                const uint32_t bOff = SW64(br, ((uint32_t)(ks * 32) + bKadd));
                LDSM_X4(bh4[pr], tBh + bOff);
                LDSM_X4(bl4[pr], tBl + bOff);
            }
#pragma unroll
            for (int mi = 0; mi < 4; mi++) {
                const int ar = aRow + mi * 16;
                const uint32_t aOff = SW64(ar, ((uint32_t)(ks * 32) + aKadd));
                uint32_t ah[4], al[4];
                LDSM_X4(ah, tAh + aOff);
                LDSM_X4(al, tAl + aOff);
                // pass 1: ah*bh
                MMA16816(c[mi][0], ah, bh4[0][0], bh4[0][1]);
                MMA16816(c[mi][1], ah, bh4[0][2], bh4[0][3]);
                MMA16816(c[mi][2], ah, bh4[1][0], bh4[1][1]);
                MMA16816(c[mi][3], ah, bh4[1][2], bh4[1][3]);
                // pass 2: ah*bl
                MMA16816(c[mi][0], ah, bl4[0][0], bl4[0][1]);
                MMA16816(c[mi][1], ah, bl4[0][2], bl4[0][3]);
                MMA16816(c[mi][2], ah, bl4[1][0], bl4[1][1]);
                MMA16816(c[mi][3], ah, bl4[1][2], bl4[1][3]);
                // pass 3: al*bh
                MMA16816(c[mi][0], al, bh4[0][0], bh4[0][1]);
                MMA16816(c[mi][1], al, bh4[0][2], bh4[0][3]);
                MMA16816(c[mi][2], al, bh4[1][0], bh4[1][1]);
                MMA16816(c[mi][3], al, bh4[1][2], bh4[1][3]);
            }
        }
        __syncthreads();
    }

    const int lr = lane >> 2;
    const int lc = (lane & 3) * 2;

    if (MODE == 0) {
#pragma unroll
        for (int mi = 0; mi < 4; mi++) {
            const int r0 = m0 + wm * 64 + mi * 16 + lr;
#pragma unroll
            for (int ni = 0; ni < 4; ni++) {
                const int col = n0 + wn * 32 + ni * 8 + lc;
                const float b0 = bias[col], b1 = bias[col + 1];
                float2 v0, v1;
                v0.x = c[mi][ni][0] + b0; v0.y = c[mi][ni][1] + b1;
                v1.x = c[mi][ni][2] + b0; v1.y = c[mi][ni][3] + b1;
                *(float2*)&Cm[(size_t)r0 * Ndim + col]       = v0;
                *(float2*)&Cm[(size_t)(r0 + 8) * Ndim + col] = v1;
            }
        }
    } else {
        // QKV epilogue: write hi/lo bf16 head-major [(b*H+h)*T + t]*D + d
        const int colbase = n0 + wn * 32;
        const int region  = colbase >> 11;          // 0=Q,1=K,2=V
        const int cr      = colbase & 2047;
        const int hh      = cr >> 7;
        const int dbase   = cr & 127;               // 0,32,64,96
        const float scale = (region == 0) ? SC_Q : 1.f;
        __nv_bfloat16 *dh, *dl;
        if (region == 0)      { dh = qhi; dl = qlo; }
        else if (region == 1) { dh = khi; dl = klo; }
        else                  { dh = vhi; dl = vlo; }
#pragma unroll
        for (int mi = 0; mi < 4; mi++) {
            const int r0 = m0 + wm * 64 + mi * 16 + lr;   // token index b*T + t
#pragma unroll
            for (int half = 0; half < 2; half++) {
                const int row = r0 + half * 8;
                const int bb  = row >> 11;
                const int tt  = row & 2047;
                const size_t base = (((size_t)(bb * H_ + hh)) * T_ + tt) * D_ + dbase;
#pragma unroll
                for (int ni = 0; ni < 4; ni++) {
                    const int col = colbase + ni * 8 + lc;
                    float v0 = (c[mi][ni][2 * half]     + bias[col])     * scale;
                    float v1 = (c[mi][ni][2 * half + 1] + bias[col + 1]) * scale;
                    uint32_t hv, lv;
                    split2(v0, v1, hv, lv);
                    *(uint32_t*)&dh[base + ni * 8 + lc] = hv;
                    *(uint32_t*)&dl[base + ni * 8 + lc] = lv;
                }
            }
        }
    }
}

// ---------------------------------------------------------------------------
// Flash attention, 512 threads (16 warps = 4/SMSP), BR=256 q-rows, BC=32.
// Each warp owns 16 q-rows (same per-warp logic as before); register softmax;
// double-buffered cp.async K/V pipeline.
// smem: Qhi 64K | Qlo 64K | 2 KV stages of (Khi|Klo|Vhi|Vlo = 32K) = 192K.
// ---------------------------------------------------------------------------
#define FQ_HI 0u
#define FQ_LO 65536u
#define FKV0  131072u
#define FKV_STAGE 32768u
#define FL_SMEM 196608

__device__ __forceinline__ void flash_load_kv(uint32_t sb, uint32_t stage,
                                              const __nv_bfloat16* kh_g,
                                              const __nv_bfloat16* kl_g,
                                              const __nv_bfloat16* vh_g,
                                              const __nv_bfloat16* vl_g,
                                              int j0, int tid)
{
    const __nv_bfloat16* srcs[4] = {
        kh_g + (size_t)j0 * D_, kl_g + (size_t)j0 * D_,
        vh_g + (size_t)j0 * D_, vl_g + (size_t)j0 * D_
    };
    // 4 tiles x 32 rows x 16 segs = 2048 slots; 512 threads x 4 iters
#pragma unroll
    for (int l = 0; l < 4; l++) {
        int idx  = tid + l * 512;
        int tile = idx >> 9;            // constant per unrolled l
        int rem  = idx & 511;
        int row  = rem >> 4;
        int seg  = rem & 15;
        CP_ASYNC16(sb + stage + (uint32_t)(tile * 8192) +
                       (uint32_t)(row * 256 + ((seg * 16) ^ ((row & 7) << 4))),
                   srcs[tile] + (size_t)row * D_ + seg * 8);
    }
    CP_COMMIT();
}

__global__ __launch_bounds__(512, 1)
void flash_reg(const __nv_bfloat16* __restrict__ qhi, const __nv_bfloat16* __restrict__ qlo,
               const __nv_bfloat16* __restrict__ khi, const __nv_bfloat16* __restrict__ klo,
               const __nv_bfloat16* __restrict__ vhi, const __nv_bfloat16* __restrict__ vlo,
               __nv_bfloat16* __restrict__ ahi, __nv_bfloat16* __restrict__ alo)
{
    extern __shared__ __align__(1024) char smf[];
    const uint32_t sb = smem_u32(smf);

    const int tid  = threadIdx.x;
    const int wid  = tid >> 5, lane = tid & 31;
    const int lr   = lane >> 2;
    const int lc   = (lane & 3) << 1;
    const int b    = blockIdx.x >> 4, h = blockIdx.x & 15;
    const int i0   = ((int)gridDim.y - 1 - (int)blockIdx.y) * 256;

    const size_t headoff = ((size_t)(b * H_ + h)) * T_ * D_;
    const __nv_bfloat16* qh_g = qhi + headoff + (size_t)i0 * D_;
    const __nv_bfloat16* ql_g = qlo + headoff + (size_t)i0 * D_;
    const __nv_bfloat16* kh_g = khi + headoff;
    const __nv_bfloat16* kl_g = klo + headoff;
    const __nv_bfloat16* vh_g = vhi + headoff;
    const __nv_bfloat16* vl_g = vlo + headoff;

    // ---- Q tiles via cp.async: 2 tiles x 256 rows x 16 segs = 8192 slots ----
    {
        const __nv_bfloat16* srcs[2] = { qh_g, ql_g };
#pragma unroll
        for (int l = 0; l < 16; l++) {
            int idx  = tid + l * 512;
            int tile = idx >> 12;       // constant per unrolled l
            int rem  = idx & 4095;
            int row  = rem >> 4;
            int seg  = rem & 15;
            CP_ASYNC16(sb + (uint32_t)(tile * 65536) +
                           (uint32_t)(row * 256 + ((seg * 16) ^ ((row & 7) << 4))),
                       srcs[tile] + (size_t)row * D_ + seg * 8);
        }
    }
    flash_load_kv(sb, FKV0, kh_g, kl_g, vh_g, vl_g, 0, tid);  // commits Q+kv0

    float o[16][4];
#pragma unroll
    for (int ni = 0; ni < 16; ni++)
#pragma unroll
        for (int e = 0; e < 4; e++) o[ni][e] = 0.f;
    float m0r = -1e30f, m1r = -1e30f, L0 = 0.f, L1 = 0.f;

    const uint32_t kxor  = (uint32_t)((lane & 7) << 4);
    const uint32_t aKadd = (uint32_t)((lane >> 4) << 4);
    const uint32_t qRow  = (uint32_t)((wid * 16 + (lane & 15)) * 256);
    const uint32_t kRowB = (uint32_t)((((lane >> 4) & 1) * 8 + (lane & 7)) * 256);
    const uint32_t bKadd = (uint32_t)(((lane >> 3) & 1) << 4);
    const uint32_t vRowB = (uint32_t)((lane & 15) * 256);
    const uint32_t vCadd = (uint32_t)(((lane >> 4) & 1) * 16);

    const int ntiles = i0 / 32 + 8;   // covers j0 <= i0 + 224 (rows to i0+255)
    for (int jt = 0; jt < ntiles; jt++) {
        const int j0 = jt * 32;
        if (jt + 1 < ntiles) {
            flash_load_kv(sb, FKV0 + (uint32_t)((jt + 1) & 1) * FKV_STAGE,
                          kh_g, kl_g, vh_g, vl_g, (jt + 1) * 32, tid);
            CP_WAIT1();
        } else {
            CP_WAIT0();
        }
        __syncthreads();

        const uint32_t stg   = FKV0 + (uint32_t)(jt & 1) * FKV_STAGE;
        const uint32_t sKhi  = stg;
        const uint32_t sKlo  = stg + 8192u;
        const uint32_t sVhi  = stg + 16384u;
        const uint32_t sVlo  = stg + 24576u;

        // ---- S = Qs @ K^T : 16 x 32 per warp ----
        float s[4][4];
#pragma unroll
        for (int ni = 0; ni < 4; ni++)
#pragma unroll
            for (int e = 0; e < 4; e++) s[ni][e] = 0.f;

#pragma unroll
        for (int ks = 0; ks < 8; ks++) {
            const uint32_t ak = ((uint32_t)(ks * 32) + aKadd) ^ kxor;
            const uint32_t bk = ((uint32_t)(ks * 32) + bKadd) ^ kxor;
            uint32_t qh[4], ql[4];
            LDSM_X4(qh, sb + FQ_HI + qRow + ak);
            LDSM_X4(ql, sb + FQ_LO + qRow + ak);
#pragma unroll
            for (int n2 = 0; n2 < 2; n2++) {
                uint32_t kh4[4], kl4[4];
                LDSM_X4(kh4, sb + sKhi + kRowB + (uint32_t)(n2 * 4096) + bk);
                LDSM_X4(kl4, sb + sKlo + kRowB + (uint32_t)(n2 * 4096) + bk);
                MMA16816(s[2 * n2],     qh, kh4[0], kh4[1]);
                MMA16816(s[2 * n2 + 1], qh, kh4[2], kh4[3]);
                MMA16816(s[2 * n2],     qh, kl4[0], kl4[1]);
                MMA16816(s[2 * n2 + 1], qh, kl4[2], kl4[3]);
                MMA16816(s[2 * n2],     ql, kh4[0], kh4[1]);
                MMA16816(s[2 * n2 + 1], ql, kh4[2], kh4[3]);
            }
        }

        // ---- causal mask (tiles overlapping/above the diagonal rows) ----
        if (jt >= ntiles - 8) {
            const int r0 = i0 + wid * 16 + lr;
#pragma unroll
            for (int ni = 0; ni < 4; ni++) {
                int cc = j0 + ni * 8 + lc;
                if (cc     > r0)     s[ni][0] = -1e30f;
                if (cc + 1 > r0)     s[ni][1] = -1e30f;
                if (cc     > r0 + 8) s[ni][2] = -1e30f;
                if (cc + 1 > r0 + 8) s[ni][3] = -1e30f;
            }
        }

        // ---- in-register online softmax (rows lr and lr+8 of this warp) ----
        float mx0 = -1e30f, mx1 = -1e30f;
#pragma unroll
        for (int ni = 0; ni < 4; ni++) {
            mx0 = fmaxf(mx0, fmaxf(s[ni][0], s[ni][1]));
            mx1 = fmaxf(mx1, fmaxf(s[ni][2], s[ni][3]));
        }
        mx0 = fmaxf(mx0, __shfl_xor_sync(0xffffffffu, mx0, 1));
        mx0 = fmaxf(mx0, __shfl_xor_sync(0xffffffffu, mx0, 2));
        mx1 = fmaxf(mx1, __shfl_xor_sync(0xffffffffu, mx1, 1));
        mx1 = fmaxf(mx1, __shfl_xor_sync(0xffffffffu, mx1, 2));
        const float mn0 = fmaxf(m0r, mx0);
        const float mn1 = fmaxf(m1r, mx1);
        const float co0 = exp2f(m0r - mn0);
        const float co1 = exp2f(m1r - mn1);
        m0r = mn0; m1r = mn1;

        float sum0 = 0.f, sum1 = 0.f;
#pragma unroll
        for (int ni = 0; ni < 4; ni++) {
            float e0 = exp2f(s[ni][0] - mn0);
            float e1 = exp2f(s[ni][1] - mn0);
            float e2 = exp2f(s[ni][2] - mn1);
            float e3 = exp2f(s[ni][3] - mn1);
            sum0 += e0 + e1; sum1 += e2 + e3;
            s[ni][0] = e0; s[ni][1] = e1; s[ni][2] = e2; s[ni][3] = e3;
        }
        sum0 += __shfl_xor_sync(0xffffffffu, sum0, 1);
        sum0 += __shfl_xor_sync(0xffffffffu, sum0, 2);
        sum1 += __shfl_xor_sync(0xffffffffu, sum1, 1);
        sum1 += __shfl_xor_sync(0xffffffffu, sum1, 2);
        L0 = L0 * co0 + sum0;
        L1 = L1 * co1 + sum1;

        // ---- rescale O ----
#pragma unroll
        for (int ni = 0; ni < 16; ni++) {
            o[ni][0] *= co0; o[ni][1] *= co0;
            o[ni][2] *= co1; o[ni][3] *= co1;
        }

        // ---- O += P @ V  (P repacked from S frags; 3-pass) ----
#pragma unroll
        for (int kb = 0; kb < 2; kb++) {
            uint32_t ph[4], pl[4];
            split2(s[2 * kb][0],     s[2 * kb][1],     ph[0], pl[0]);
            split2(s[2 * kb][2],     s[2 * kb][3],     ph[1], pl[1]);
            split2(s[2 * kb + 1][0], s[2 * kb + 1][1], ph[2], pl[2]);
            split2(s[2 * kb + 1][2], s[2 * kb + 1][3], ph[3], pl[3]);
            const uint32_t vrb = (uint32_t)(kb * 16 * 256) + vRowB;
#pragma unroll
            for (int n2 = 0; n2 < 8; n2++) {
                uint32_t vh4[4], vl4[4];
                const uint32_t cbo = (((uint32_t)(n2 * 32) + vCadd) ^ kxor);
                LDSM_X4_T(vh4, sb + sVhi + vrb + cbo);
                LDSM_X4_T(vl4, sb + sVlo + vrb + cbo);
                MMA16816(o[2 * n2],     ph, vh4[0], vh4[1]);
                MMA16816(o[2 * n2 + 1], ph, vh4[2], vh4[3]);
                MMA16816(o[2 * n2],     ph, vl4[0], vl4[1]);
                MMA16816(o[2 * n2 + 1], ph, vl4[2], vl4[3]);
                MMA16816(o[2 * n2],     pl, vh4[0], vh4[1]);
                MMA16816(o[2 * n2 + 1], pl, vh4[2], vh4[3]);
            }
        }
        __syncthreads();
    }

    // ---- epilogue: normalize, split to bf16 hi/lo, token-major [t, C] ----
    {
        const float i0v = 1.f / L0;
        const float i1v = 1.f / L1;
        const size_t ra = (size_t)(b * T_ + i0 + wid * 16 + lr) * C_ + h * D_;
        const size_t rb = ra + (size_t)8 * C_;
#pragma unroll
        for (int ni = 0; ni < 16; ni++) {
            uint32_t hv, lv;
            split2(o[ni][0] * i0v, o[ni][1] * i0v, hv, lv);
            *(uint32_t*)&ahi[ra + ni * 8 + lc] = hv;
            *(uint32_t*)&alo[ra + ni * 8 + lc] = lv;
            split2(o[ni][2] * i1v, o[ni][3] * i1v, hv, lv);
            *(uint32_t*)&ahi[rb + ni * 8 + lc] = hv;
            *(uint32_t*)&alo[rb + ni * 8 + lc] = lv;
        }
    }
}

// ---------------------------------------------------------------------------
// Launch
// ---------------------------------------------------------------------------
extern "C" void kernel_launch(void* const* d_in, const int* in_sizes, int n_in,
                              void* d_out, int out_size)
{
    const float* x     = (const float*)d_in[0];
    const float* Wqkv  = (const float*)d_in[1];
    const float* bqkv  = (const float*)d_in[2];
    const float* Wproj = (const float*)d_in[3];
    const float* bproj = (const float*)d_in[4];
    float* out = (float*)d_out;

    __nv_bfloat16 *xhi, *xlo, *w1hi, *w1lo, *w2hi, *w2lo;
    __nv_bfloat16 *qhi, *qlo, *khi, *klo, *vhi, *vlo, *ahi, *alo;
    cudaGetSymbolAddress((void**)&xhi,  g_xhi);
    cudaGetSymbolAddress((void**)&xlo,  g_xlo);
    cudaGetSymbolAddress((void**)&w1hi, g_w1hi);
    cudaGetSymbolAddress((void**)&w1lo, g_w1lo);
    cudaGetSymbolAddress((void**)&w2hi, g_w2hi);
    cudaGetSymbolAddress((void**)&w2lo, g_w2lo);
    cudaGetSymbolAddress((void**)&qhi,  g_qhi);
    cudaGetSymbolAddress((void**)&qlo,  g_qlo);
    cudaGetSymbolAddress((void**)&khi,  g_khi);
    cudaGetSymbolAddress((void**)&klo,  g_klo);
    cudaGetSymbolAddress((void**)&vhi,  g_vhi);
    cudaGetSymbolAddress((void**)&vlo,  g_vlo);
    cudaGetSymbolAddress((void**)&ahi,  g_ahi);
    cudaGetSymbolAddress((void**)&alo,  g_alo);

    cudaFuncSetAttribute(mma_gemm<0>, cudaFuncAttributeMaxDynamicSharedMemorySize,
                         GEMM_SMEM);
    cudaFuncSetAttribute(mma_gemm<1>, cudaFuncAttributeMaxDynamicSharedMemorySize,
                         GEMM_SMEM);
    cudaFuncSetAttribute(flash_reg, cudaFuncAttributeMaxDynamicSharedMemorySize,
                         FL_SMEM);

    const int n4x = (M_ * C_) / 4;

    split_kernel<<<n4x / 256, 256>>>(x, xhi, xlo, n4x);
    split_transpose_kernel<<<dim3(N1_ / 32, C_ / 32), dim3(32, 8)>>>(Wqkv, w1hi, w1lo, C_, N1_);
    split_transpose_kernel<<<dim3(C_ / 32, C_ / 32), dim3(32, 8)>>>(Wproj, w2hi, w2lo, C_, C_);

    // 1) QKV GEMM -> split bf16 Q(scaled)/K/V head-major
    mma_gemm<1><<<dim3(N1_ / 128, M_ / 128), 256, GEMM_SMEM>>>(
        xhi, xlo, w1hi, w1lo, bqkv, nullptr,
        qhi, qlo, khi, klo, vhi, vlo, N1_, C_);

    // 2) causal flash attention -> split bf16 att  (512 threads, BR=256)
    flash_reg<<<dim3(B_ * H_, T_ / 256), 512, FL_SMEM>>>(
        qhi, qlo, khi, klo, vhi, vlo, ahi, alo);

    // 3) proj GEMM -> fp32 out
    mma_gemm<0><<<dim3(C_ / 128, M_ / 128), 256, GEMM_SMEM>>>(
        ahi, alo, w2hi, w2lo, bproj, out,
        nullptr, nullptr, nullptr, nullptr, nullptr, nullptr, C_, C_);
}

// round 14
// speedup vs baseline: 1.3281x; 1.3281x over previous
#include <cuda_runtime.h>
#include <cuda_bf16.h>
#include <cuda_fp16.h>
#include <cstdint>
#include <cstddef>

// Problem constants (B=4, T=2048, C=2048, H=16, D=128)
#define B_  4
#define T_  2048
#define C_  2048
#define H_  16
#define D_  128
#define M_  (B_ * T_)       // 8192
#define N1_ (3 * C_)        // 6144

// softmax scale * log2(e)  (folded into Q at QKV-GEMM epilogue)
#define SC_Q (0.08838834764831844f * 1.44269504088896340736f)

// ---------------------------------------------------------------------------
// Scratch (__device__ globals; no allocs allowed)
// ---------------------------------------------------------------------------
__device__ __half g_xh[(size_t)M_ * C_];        // x fp16 hi
__device__ __half g_xl[(size_t)M_ * C_];        // x fp16 lo (residual)
__device__ __half g_w1[(size_t)N1_ * C_];       // Wqkv^T fp16 [6144,2048]
__device__ __half g_w2[(size_t)C_ * C_];        // Wproj^T fp16 [2048,2048]
// head-major Q/K/V (bf16 hi/lo, consumed by flash): [(b*H+h)*T + t]*D + d
__device__ __nv_bfloat16 g_qhi[(size_t)M_ * C_];
__device__ __nv_bfloat16 g_qlo[(size_t)M_ * C_];
__device__ __nv_bfloat16 g_khi[(size_t)M_ * C_];
__device__ __nv_bfloat16 g_klo[(size_t)M_ * C_];
__device__ __nv_bfloat16 g_vhi[(size_t)M_ * C_];
__device__ __nv_bfloat16 g_vlo[(size_t)M_ * C_];
// attention output fp16 hi/lo (token-major [t, C]), feeds proj GEMM
__device__ __half g_ah[(size_t)M_ * C_];
__device__ __half g_al[(size_t)M_ * C_];

// ---------------------------------------------------------------------------
// Helpers
// ---------------------------------------------------------------------------
__device__ __forceinline__ uint32_t smem_u32(const void* p) {
    uint32_t a;
    asm("{ .reg .u64 t; cvta.to.shared.u64 t, %1; cvt.u32.u64 %0, t; }"
        : "=r"(a) : "l"(p));
    return a;
}

#define LDSM_X4(r, a)                                                          \
    asm volatile("ldmatrix.sync.aligned.m8n8.x4.shared.b16 {%0,%1,%2,%3}, [%4];" \
        : "=r"((r)[0]), "=r"((r)[1]), "=r"((r)[2]), "=r"((r)[3]) : "r"(a))

#define LDSM_X4_T(r, a)                                                        \
    asm volatile("ldmatrix.sync.aligned.m8n8.x4.trans.shared.b16 {%0,%1,%2,%3}, [%4];" \
        : "=r"((r)[0]), "=r"((r)[1]), "=r"((r)[2]), "=r"((r)[3]) : "r"(a))

// bf16 MMA (flash)
#define MMA16816(c, a, b0v, b1v)                                               \
    asm volatile("mma.sync.aligned.m16n8k16.row.col.f32.bf16.bf16.f32 "        \
        "{%0,%1,%2,%3}, {%4,%5,%6,%7}, {%8,%9}, {%0,%1,%2,%3};"                \
        : "+f"((c)[0]), "+f"((c)[1]), "+f"((c)[2]), "+f"((c)[3])               \
        : "r"((a)[0]), "r"((a)[1]), "r"((a)[2]), "r"((a)[3]),                  \
          "r"(b0v), "r"(b1v))

// fp16 MMA (weight GEMMs)
#define MMA16816H(c, a, b0v, b1v)                                              \
    asm volatile("mma.sync.aligned.m16n8k16.row.col.f32.f16.f16.f32 "          \
        "{%0,%1,%2,%3}, {%4,%5,%6,%7}, {%8,%9}, {%0,%1,%2,%3};"                \
        : "+f"((c)[0]), "+f"((c)[1]), "+f"((c)[2]), "+f"((c)[3])               \
        : "r"((a)[0]), "r"((a)[1]), "r"((a)[2]), "r"((a)[3]),                  \
          "r"(b0v), "r"(b1v))

#define CP_ASYNC16(dst, src)                                                   \
    asm volatile("cp.async.cg.shared.global [%0], [%1], 16;"                   \
        :: "r"(dst), "l"(src))
#define CP_COMMIT()  asm volatile("cp.async.commit_group;" ::: "memory")
#define CP_WAIT1()   asm volatile("cp.async.wait_group 1;" ::: "memory")
#define CP_WAIT0()   asm volatile("cp.async.wait_group 0;" ::: "memory")

__device__ __forceinline__ uint32_t pack_bf2(float a, float b) {
    __nv_bfloat162 t = __halves2bfloat162(__float2bfloat16_rn(a),
                                          __float2bfloat16_rn(b));
    return *(uint32_t*)&t;
}

// bf16 split (flash P / QKV epilogue)
__device__ __forceinline__ void split2(float a, float b, uint32_t& h, uint32_t& l) {
    __nv_bfloat16 ha = __float2bfloat16_rn(a);
    __nv_bfloat16 hb = __float2bfloat16_rn(b);
    __nv_bfloat162 th = __halves2bfloat162(ha, hb);
    h = *(uint32_t*)&th;
    l = pack_bf2(a - __bfloat162float(ha), b - __bfloat162float(hb));
}

// fp16 split (GEMM A operands)
__device__ __forceinline__ void split2h(float a, float b, uint32_t& h, uint32_t& l) {
    __half ha = __float2half_rn(a);
    __half hb = __float2half_rn(b);
    __half2 th = __halves2half2(ha, hb);
    h = *(uint32_t*)&th;
    __half2 tl = __halves2half2(__float2half_rn(a - __half2float(ha)),
                                __float2half_rn(b - __half2float(hb)));
    l = *(uint32_t*)&tl;
}

// ---------------------------------------------------------------------------
// Split fp32 -> fp16 hi/lo (for x)
// ---------------------------------------------------------------------------
__global__ void split_kernel_h(const float* __restrict__ in,
                               __half* __restrict__ hi,
                               __half* __restrict__ lo, int n4)
{
    int i = blockIdx.x * blockDim.x + threadIdx.x;
    if (i >= n4) return;
    float4 v = ((const float4*)in)[i];
    uint32_t h0, l0, h1, l1;
    split2h(v.x, v.y, h0, l0);
    split2h(v.z, v.w, h1, l1);
    uint32_t* H = (uint32_t*)hi;
    uint32_t* L = (uint32_t*)lo;
    H[2 * i] = h0; H[2 * i + 1] = h1;
    L[2 * i] = l0; L[2 * i + 1] = l1;
}

// ---------------------------------------------------------------------------
// Transpose: W[K,N] fp32 -> W^T fp16 [N,K] (single precision copy)
// ---------------------------------------------------------------------------
__global__ __launch_bounds__(256)
void transpose_h_kernel(const float* __restrict__ W,
                        __half* __restrict__ hT, int K, int N)
{
    __shared__ float t[32][33];
    const int n0 = blockIdx.x * 32, k0 = blockIdx.y * 32;
    const int tx = threadIdx.x, ty = threadIdx.y;
#pragma unroll
    for (int j = 0; j < 4; j++)
        t[ty + j * 8][tx] = W[(size_t)(k0 + ty + j * 8) * N + n0 + tx];
    __syncthreads();
#pragma unroll
    for (int j = 0; j < 4; j++) {
        float v = t[tx][ty + j * 8];
        hT[(size_t)(n0 + ty + j * 8) * K + k0 + tx] = __float2half_rn(v);
    }
}

// ---------------------------------------------------------------------------
// fp16 2-pass GEMM: C = (Ah + Al) @ B^T + bias, A fp16 hi/lo [M,K], B fp16 [N,K].
// CTA tile 128x128, 8 warps of 64x32, K-chunk 32, double-buffered, 2 CTAs/SM.
// Stage: Ah 8K | Al 8K | B 8K = 24K; 2 stages = 48K/CTA.
// 64B rows, swizzle SW64 (validated): conflict-free ldsm.
// MODE 0: fp32 out + bias (proj). MODE 1: QKV split-bf16 head-major epilogue.
// ---------------------------------------------------------------------------
#define GH_STAGE 24576u
#define GEMM_SMEM (2 * 24576)

#define SW64(row, segb) ((uint32_t)((row) * 64) + (((uint32_t)(segb)) ^ ((((uint32_t)(row) >> 1) & 3u) << 4)))

__device__ __forceinline__ void load_chunk_h(uint32_t sb, int buf,
                                             const __half* aH, const __half* aL,
                                             const __half* bB,
                                             int k0, int Kdim, int tid)
{
    const uint32_t st = sb + (uint32_t)buf * GH_STAGE;
    const __half* srcs[3] = { aH, aL, bB };
#pragma unroll
    for (int tl = 0; tl < 3; tl++) {
        const __half* s = srcs[tl] + k0;
        const uint32_t tb = st + (uint32_t)tl * 8192u;
#pragma unroll
        for (int l = 0; l < 2; l++) {
            int idx = tid + l * 256;          // 512 slots: 128 rows x 4 segs
            int row = idx >> 2, seg = idx & 3;
            CP_ASYNC16(tb + SW64(row, seg * 16),
                       s + (size_t)row * Kdim + seg * 8);
        }
    }
    CP_COMMIT();
}

template <int MODE>
__global__ __launch_bounds__(256, 2)
void mma_gemm(const __half* __restrict__ Ah, const __half* __restrict__ Al,
              const __half* __restrict__ Bm,
              const float* __restrict__ bias, float* __restrict__ Cm,
              __nv_bfloat16* __restrict__ qhi, __nv_bfloat16* __restrict__ qlo,
              __nv_bfloat16* __restrict__ khi, __nv_bfloat16* __restrict__ klo,
              __nv_bfloat16* __restrict__ vhi, __nv_bfloat16* __restrict__ vlo,
              int Ndim, int Kdim)
{
    extern __shared__ __align__(128) char smem[];
    const uint32_t sb = smem_u32(smem);
    const int tid  = threadIdx.x;
    const int wid  = tid >> 5;
    const int lane = tid & 31;
    const int wm   = wid & 1;        // 0..1 -> 64 rows
    const int wn   = wid >> 1;       // 0..3 -> 32 cols
    const int m0   = blockIdx.y * 128;
    const int n0   = blockIdx.x * 128;

    const __half* aH = Ah + (size_t)m0 * Kdim;
    const __half* aL = Al + (size_t)m0 * Kdim;
    const __half* bB = Bm + (size_t)n0 * Kdim;

    const int aRow = wm * 64 + (lane & 15);
    const uint32_t aKadd = (uint32_t)((lane >> 4) << 4);
    const int bRowB = wn * 32 + ((lane >> 4) & 1) * 8 + (lane & 7);
    const uint32_t bKadd = (uint32_t)(((lane >> 3) & 1) << 4);

    float c[4][4][4];
#pragma unroll
    for (int mi = 0; mi < 4; mi++)
#pragma unroll
        for (int ni = 0; ni < 4; ni++)
#pragma unroll
            for (int e = 0; e < 4; e++) c[mi][ni][e] = 0.f;

    const int nch = Kdim >> 5;       // K-chunks of 32
    load_chunk_h(sb, 0, aH, aL, bB, 0, Kdim, tid);

    for (int t = 0; t < nch; t++) {
        if (t + 1 < nch) {
            load_chunk_h(sb, (t + 1) & 1, aH, aL, bB, (t + 1) << 5, Kdim, tid);
            CP_WAIT1();
        } else {
            CP_WAIT0();
        }
        __syncthreads();

        const uint32_t st  = sb + (uint32_t)(t & 1) * GH_STAGE;
        const uint32_t tAh = st;
        const uint32_t tAl = st + 8192u;
        const uint32_t tB  = st + 16384u;

#pragma unroll
        for (int ks = 0; ks < 2; ks++) {
            uint32_t b4[2][4];
#pragma unroll
            for (int pr = 0; pr < 2; pr++) {
                const int br = bRowB + pr * 16;
                LDSM_X4(b4[pr], tB + SW64(br, ((uint32_t)(ks * 32) + bKadd)));
            }
#pragma unroll
            for (int mi = 0; mi < 4; mi++) {
                const int ar = aRow + mi * 16;
                const uint32_t aOff = SW64(ar, ((uint32_t)(ks * 32) + aKadd));
                uint32_t ah[4], al[4];
                LDSM_X4(ah, tAh + aOff);
                LDSM_X4(al, tAl + aOff);
                // pass 1: ah * B
                MMA16816H(c[mi][0], ah, b4[0][0], b4[0][1]);
                MMA16816H(c[mi][1], ah, b4[0][2], b4[0][3]);
                MMA16816H(c[mi][2], ah, b4[1][0], b4[1][1]);
                MMA16816H(c[mi][3], ah, b4[1][2], b4[1][3]);
                // pass 2: al * B
                MMA16816H(c[mi][0], al, b4[0][0], b4[0][1]);
                MMA16816H(c[mi][1], al, b4[0][2], b4[0][3]);
                MMA16816H(c[mi][2], al, b4[1][0], b4[1][1]);
                MMA16816H(c[mi][3], al, b4[1][2], b4[1][3]);
            }
        }
        __syncthreads();
    }

    const int lr = lane >> 2;
    const int lc = (lane & 3) * 2;

    if (MODE == 0) {
#pragma unroll
        for (int mi = 0; mi < 4; mi++) {
            const int r0 = m0 + wm * 64 + mi * 16 + lr;
#pragma unroll
            for (int ni = 0; ni < 4; ni++) {
                const int col = n0 + wn * 32 + ni * 8 + lc;
                const float b0 = bias[col], b1 = bias[col + 1];
                float2 v0, v1;
                v0.x = c[mi][ni][0] + b0; v0.y = c[mi][ni][1] + b1;
                v1.x = c[mi][ni][2] + b0; v1.y = c[mi][ni][3] + b1;
                *(float2*)&Cm[(size_t)r0 * Ndim + col]       = v0;
                *(float2*)&Cm[(size_t)(r0 + 8) * Ndim + col] = v1;
            }
        }
    } else {
        // QKV epilogue: write hi/lo bf16 head-major [(b*H+h)*T + t]*D + d
        const int colbase = n0 + wn * 32;
        const int region  = colbase >> 11;          // 0=Q,1=K,2=V
        const int cr      = colbase & 2047;
        const int hh      = cr >> 7;
        const int dbase   = cr & 127;               // 0,32,64,96
        const float scale = (region == 0) ? SC_Q : 1.f;
        __nv_bfloat16 *dh, *dl;
        if (region == 0)      { dh = qhi; dl = qlo; }
        else if (region == 1) { dh = khi; dl = klo; }
        else                  { dh = vhi; dl = vlo; }
#pragma unroll
        for (int mi = 0; mi < 4; mi++) {
            const int r0 = m0 + wm * 64 + mi * 16 + lr;   // token index b*T + t
#pragma unroll
            for (int half = 0; half < 2; half++) {
                const int row = r0 + half * 8;
                const int bb  = row >> 11;
                const int tt  = row & 2047;
                const size_t base = (((size_t)(bb * H_ + hh)) * T_ + tt) * D_ + dbase;
#pragma unroll
                for (int ni = 0; ni < 4; ni++) {
                    const int col = colbase + ni * 8 + lc;
                    float v0 = (c[mi][ni][2 * half]     + bias[col])     * scale;
                    float v1 = (c[mi][ni][2 * half + 1] + bias[col + 1]) * scale;
                    uint32_t hv, lv;
                    split2(v0, v1, hv, lv);
                    *(uint32_t*)&dh[base + ni * 8 + lc] = hv;
                    *(uint32_t*)&dl[base + ni * 8 + lc] = lv;
                }
            }
        }
    }
}

// ---------------------------------------------------------------------------
// Flash attention (proven R7 version): 256 threads, BR=128, BC=64, register
// softmax, bf16 hi/lo operands from gmem, double-buffered cp.async KV pipeline.
// Epilogue writes fp16 hi/lo for the 2-pass proj GEMM.
// smem: Qhi 32K | Qlo 32K | 2 KV stages of (Khi|Klo|Vhi|Vlo = 64K) = 192K.
// ---------------------------------------------------------------------------
#define FQ_HI 0u
#define FQ_LO 32768u
#define FKV0  65536u
#define FKV_STAGE 65536u
#define FL_SMEM 196608

__device__ __forceinline__ void flash_load_kv(uint32_t sb, uint32_t stage,
                                              const __nv_bfloat16* kh_g,
                                              const __nv_bfloat16* kl_g,
                                              const __nv_bfloat16* vh_g,
                                              const __nv_bfloat16* vl_g,
                                              int j0, int tid)
{
    const __nv_bfloat16* srcs[4] = {
        kh_g + (size_t)j0 * D_, kl_g + (size_t)j0 * D_,
        vh_g + (size_t)j0 * D_, vl_g + (size_t)j0 * D_
    };
#pragma unroll
    for (int l = 0; l < 16; l++) {
        int idx  = tid + l * 256;
        int tile = idx >> 10;
        int rem  = idx & 1023;
        int row  = rem >> 4;
        int seg  = rem & 15;
        CP_ASYNC16(sb + stage + (uint32_t)(tile * 16384) +
                       (uint32_t)(row * 256 + ((seg * 16) ^ ((row & 7) << 4))),
                   srcs[tile] + (size_t)row * D_ + seg * 8);
    }
    CP_COMMIT();
}

__global__ __launch_bounds__(256, 1)
void flash_reg(const __nv_bfloat16* __restrict__ qhi, const __nv_bfloat16* __restrict__ qlo,
               const __nv_bfloat16* __restrict__ khi, const __nv_bfloat16* __restrict__ klo,
               const __nv_bfloat16* __restrict__ vhi, const __nv_bfloat16* __restrict__ vlo,
               __half* __restrict__ ah_out, __half* __restrict__ al_out)
{
    extern __shared__ __align__(1024) char smf[];
    const uint32_t sb = smem_u32(smf);

    const int tid  = threadIdx.x;
    const int wid  = tid >> 5, lane = tid & 31;
    const int lr   = lane >> 2;
    const int lc   = (lane & 3) << 1;
    const int b    = blockIdx.x >> 4, h = blockIdx.x & 15;
    const int i0   = ((int)gridDim.y - 1 - (int)blockIdx.y) * 128;

    const size_t headoff = ((size_t)(b * H_ + h)) * T_ * D_;
    const __nv_bfloat16* qh_g = qhi + headoff + (size_t)i0 * D_;
    const __nv_bfloat16* ql_g = qlo + headoff + (size_t)i0 * D_;
    const __nv_bfloat16* kh_g = khi + headoff;
    const __nv_bfloat16* kl_g = klo + headoff;
    const __nv_bfloat16* vh_g = vhi + headoff;
    const __nv_bfloat16* vl_g = vlo + headoff;

    {
        const __nv_bfloat16* srcs[2] = { qh_g, ql_g };
#pragma unroll
        for (int l = 0; l < 16; l++) {
            int idx  = tid + l * 256;
            int tile = idx >> 11;
            int rem  = idx & 2047;
            int row  = rem >> 4;
            int seg  = rem & 15;
            CP_ASYNC16(sb + (uint32_t)(tile * 32768) +
                           (uint32_t)(row * 256 + ((seg * 16) ^ ((row & 7) << 4))),
                       srcs[tile] + (size_t)row * D_ + seg * 8);
        }
    }
    flash_load_kv(sb, FKV0, kh_g, kl_g, vh_g, vl_g, 0, tid);

    float o[16][4];
#pragma unroll
    for (int ni = 0; ni < 16; ni++)
#pragma unroll
        for (int e = 0; e < 4; e++) o[ni][e] = 0.f;
    float m0r = -1e30f, m1r = -1e30f, L0 = 0.f, L1 = 0.f;

    const uint32_t kxor  = (uint32_t)((lane & 7) << 4);
    const uint32_t aKadd = (uint32_t)((lane >> 4) << 4);
    const uint32_t qRow  = (uint32_t)((wid * 16 + (lane & 15)) * 256);
    const uint32_t kRowB = (uint32_t)((((lane >> 4) & 1) * 8 + (lane & 7)) * 256);
    const uint32_t bKadd = (uint32_t)(((lane >> 3) & 1) << 4);
    const uint32_t vRowB = (uint32_t)((lane & 15) * 256);
    const uint32_t vCadd = (uint32_t)(((lane >> 4) & 1) * 16);

    const int ntiles = i0 / 64 + 2;
    for (int jt = 0; jt < ntiles; jt++) {
        const int j0 = jt * 64;
        if (jt + 1 < ntiles) {
            flash_load_kv(sb, FKV0 + (uint32_t)((jt + 1) & 1) * FKV_STAGE,
                          kh_g, kl_g, vh_g, vl_g, (jt + 1) * 64, tid);
            CP_WAIT1();
        } else {
            CP_WAIT0();
        }
        __syncthreads();

        const uint32_t stg   = FKV0 + (uint32_t)(jt & 1) * FKV_STAGE;
        const uint32_t sKhi  = stg;
        const uint32_t sKlo  = stg + 16384u;
        const uint32_t sVhi  = stg + 32768u;
        const uint32_t sVlo  = stg + 49152u;

        float s[8][4];
#pragma unroll
        for (int ni = 0; ni < 8; ni++)
#pragma unroll
            for (int e = 0; e < 4; e++) s[ni][e] = 0.f;

#pragma unroll
        for (int ks = 0; ks < 8; ks++) {
            const uint32_t ak = ((uint32_t)(ks * 32) + aKadd) ^ kxor;
            const uint32_t bk = ((uint32_t)(ks * 32) + bKadd) ^ kxor;
            uint32_t qh[4], ql[4];
            LDSM_X4(qh, sb + FQ_HI + qRow + ak);
            LDSM_X4(ql, sb + FQ_LO + qRow + ak);
#pragma unroll
            for (int n2 = 0; n2 < 4; n2++) {
                uint32_t kh4[4], kl4[4];
                LDSM_X4(kh4, sb + sKhi + kRowB + (uint32_t)(n2 * 4096) + bk);
                LDSM_X4(kl4, sb + sKlo + kRowB + (uint32_t)(n2 * 4096) + bk);
                MMA16816(s[2 * n2],     qh, kh4[0], kh4[1]);
                MMA16816(s[2 * n2 + 1], qh, kh4[2], kh4[3]);
                MMA16816(s[2 * n2],     qh, kl4[0], kl4[1]);
                MMA16816(s[2 * n2 + 1], qh, kl4[2], kl4[3]);
                MMA16816(s[2 * n2],     ql, kh4[0], kh4[1]);
                MMA16816(s[2 * n2 + 1], ql, kh4[2], kh4[3]);
            }
        }

        if (jt >= ntiles - 2) {
            const int r0 = i0 + wid * 16 + lr;
#pragma unroll
            for (int ni = 0; ni < 8; ni++) {
                int cc = j0 + ni * 8 + lc;
                if (cc     > r0)     s[ni][0] = -1e30f;
                if (cc + 1 > r0)     s[ni][1] = -1e30f;
                if (cc     > r0 + 8) s[ni][2] = -1e30f;
                if (cc + 1 > r0 + 8) s[ni][3] = -1e30f;
            }
        }

        float mx0 = -1e30f, mx1 = -1e30f;
#pragma unroll
        for (int ni = 0; ni < 8; ni++) {
            mx0 = fmaxf(mx0, fmaxf(s[ni][0], s[ni][1]));
            mx1 = fmaxf(mx1, fmaxf(s[ni][2], s[ni][3]));
        }
        mx0 = fmaxf(mx0, __shfl_xor_sync(0xffffffffu, mx0, 1));
        mx0 = fmaxf(mx0, __shfl_xor_sync(0xffffffffu, mx0, 2));
        mx1 = fmaxf(mx1, __shfl_xor_sync(0xffffffffu, mx1, 1));
        mx1 = fmaxf(mx1, __shfl_xor_sync(0xffffffffu, mx1, 2));
        const float mn0 = fmaxf(m0r, mx0);
        const float mn1 = fmaxf(m1r, mx1);
        const float co0 = exp2f(m0r - mn0);
        const float co1 = exp2f(m1r - mn1);
        m0r = mn0; m1r = mn1;

        float sum0 = 0.f, sum1 = 0.f;
#pragma unroll
        for (int ni = 0; ni < 8; ni++) {
            float e0 = exp2f(s[ni][0] - mn0);
            float e1 = exp2f(s[ni][1] - mn0);
            float e2 = exp2f(s[ni][2] - mn1);
            float e3 = exp2f(s[ni][3] - mn1);
            sum0 += e0 + e1; sum1 += e2 + e3;
            s[ni][0] = e0; s[ni][1] = e1; s[ni][2] = e2; s[ni][3] = e3;
        }
        sum0 += __shfl_xor_sync(0xffffffffu, sum0, 1);
        sum0 += __shfl_xor_sync(0xffffffffu, sum0, 2);
        sum1 += __shfl_xor_sync(0xffffffffu, sum1, 1);
        sum1 += __shfl_xor_sync(0xffffffffu, sum1, 2);
        L0 = L0 * co0 + sum0;
        L1 = L1 * co1 + sum1;

#pragma unroll
        for (int ni = 0; ni < 16; ni++) {
            o[ni][0] *= co0; o[ni][1] *= co0;
            o[ni][2] *= co1; o[ni][3] *= co1;
        }

#pragma unroll
        for (int kb = 0; kb < 4; kb++) {
            uint32_t ph[4], pl[4];
            split2(s[2 * kb][0],     s[2 * kb][1],     ph[0], pl[0]);
            split2(s[2 * kb][2],     s[2 * kb][3],     ph[1], pl[1]);
            split2(s[2 * kb + 1][0], s[2 * kb + 1][1], ph[2], pl[2]);
            split2(s[2 * kb + 1][2], s[2 * kb + 1][3], ph[3], pl[3]);
            const uint32_t vrb = (uint32_t)(kb * 16 * 256) + vRowB;
#pragma unroll
            for (int n2 = 0; n2 < 8; n2++) {
                uint32_t vh4[4], vl4[4];
                const uint32_t cbo = (((uint32_t)(n2 * 32) + vCadd) ^ kxor);
                LDSM_X4_T(vh4, sb + sVhi + vrb + cbo);
                LDSM_X4_T(vl4, sb + sVlo + vrb + cbo);
                MMA16816(o[2 * n2],     ph, vh4[0], vh4[1]);
                MMA16816(o[2 * n2 + 1], ph, vh4[2], vh4[3]);
                MMA16816(o[2 * n2],     ph, vl4[0], vl4[1]);
                MMA16816(o[2 * n2 + 1], ph, vl4[2], vl4[3]);
                MMA16816(o[2 * n2],     pl, vh4[0], vh4[1]);
                MMA16816(o[2 * n2 + 1], pl, vh4[2], vh4[3]);
            }
        }
        __syncthreads();
    }

    // ---- epilogue: normalize, split to fp16 hi/lo, token-major [t, C] ----
    {
        const float i0v = 1.f / L0;
        const float i1v = 1.f / L1;
        const size_t ra = (size_t)(b * T_ + i0 + wid * 16 + lr) * C_ + h * D_;
        const size_t rb = ra + (size_t)8 * C_;
#pragma unroll
        for (int ni = 0; ni < 16; ni++) {
            uint32_t hv, lv;
            split2h(o[ni][0] * i0v, o[ni][1] * i0v, hv, lv);
            *(uint32_t*)&ah_out[ra + ni * 8 + lc] = hv;
            *(uint32_t*)&al_out[ra + ni * 8 + lc] = lv;
            split2h(o[ni][2] * i1v, o[ni][3] * i1v, hv, lv);
            *(uint32_t*)&ah_out[rb + ni * 8 + lc] = hv;
            *(uint32_t*)&al_out[rb + ni * 8 + lc] = lv;
        }
    }
}

// ---------------------------------------------------------------------------
// Launch
// ---------------------------------------------------------------------------
extern "C" void kernel_launch(void* const* d_in, const int* in_sizes, int n_in,
                              void* d_out, int out_size)
{
    const float* x     = (const float*)d_in[0];
    const float* Wqkv  = (const float*)d_in[1];
    const float* bqkv  = (const float*)d_in[2];
    const float* Wproj = (const float*)d_in[3];
    const float* bproj = (const float*)d_in[4];
    float* out = (float*)d_out;

    __half *xh, *xl, *w1, *w2, *ah, *al;
    __nv_bfloat16 *qhi, *qlo, *khi, *klo, *vhi, *vlo;
    cudaGetSymbolAddress((void**)&xh,  g_xh);
    cudaGetSymbolAddress((void**)&xl,  g_xl);
    cudaGetSymbolAddress((void**)&w1,  g_w1);
    cudaGetSymbolAddress((void**)&w2,  g_w2);
    cudaGetSymbolAddress((void**)&ah,  g_ah);
    cudaGetSymbolAddress((void**)&al,  g_al);
    cudaGetSymbolAddress((void**)&qhi, g_qhi);
    cudaGetSymbolAddress((void**)&qlo, g_qlo);
    cudaGetSymbolAddress((void**)&khi, g_khi);
    cudaGetSymbolAddress((void**)&klo, g_klo);
    cudaGetSymbolAddress((void**)&vhi, g_vhi);
    cudaGetSymbolAddress((void**)&vlo, g_vlo);

    cudaFuncSetAttribute(mma_gemm<0>, cudaFuncAttributeMaxDynamicSharedMemorySize,
                         GEMM_SMEM);
    cudaFuncSetAttribute(mma_gemm<1>, cudaFuncAttributeMaxDynamicSharedMemorySize,
                         GEMM_SMEM);
    cudaFuncSetAttribute(flash_reg, cudaFuncAttributeMaxDynamicSharedMemorySize,
                         FL_SMEM);

    const int n4x = (M_ * C_) / 4;

    // x -> fp16 hi/lo; weights -> transposed fp16
    split_kernel_h<<<n4x / 256, 256>>>(x, xh, xl, n4x);
    transpose_h_kernel<<<dim3(N1_ / 32, C_ / 32), dim3(32, 8)>>>(Wqkv, w1, C_, N1_);
    transpose_h_kernel<<<dim3(C_ / 32, C_ / 32), dim3(32, 8)>>>(Wproj, w2, C_, C_);

    // 1) QKV GEMM (fp16 2-pass) -> split bf16 Q(scaled)/K/V head-major
    mma_gemm<1><<<dim3(N1_ / 128, M_ / 128), 256, GEMM_SMEM>>>(
        xh, xl, w1, bqkv, nullptr,
        qhi, qlo, khi, klo, vhi, vlo, N1_, C_);

    // 2) causal flash attention (bf16 3-pass) -> fp16 hi/lo att
    flash_reg<<<dim3(B_ * H_, T_ / 128), 256, FL_SMEM>>>(
        qhi, qlo, khi, klo, vhi, vlo, ah, al);

    // 3) proj GEMM (fp16 2-pass) -> fp32 out
    mma_gemm<0><<<dim3(C_ / 128, M_ / 128), 256, GEMM_SMEM>>>(
        ah, al, w2, bproj, out,
        nullptr, nullptr, nullptr, nullptr, nullptr, nullptr, C_, C_);
}

// round 15
// speedup vs baseline: 1.4505x; 1.0921x over previous
#include <cuda_runtime.h>
#include <cuda_bf16.h>
#include <cuda_fp16.h>
#include <cstdint>
#include <cstddef>

// Problem constants (B=4, T=2048, C=2048, H=16, D=128)
#define B_  4
#define T_  2048
#define C_  2048
#define H_  16
#define D_  128
#define M_  (B_ * T_)       // 8192
#define N1_ (3 * C_)        // 6144

// softmax scale * log2(e)  (folded into Q at QKV-GEMM epilogue)
#define SC_Q (0.08838834764831844f * 1.44269504088896340736f)

// ---------------------------------------------------------------------------
// Scratch (__device__ globals; no allocs allowed)
// ---------------------------------------------------------------------------
__device__ __half g_xh[(size_t)M_ * C_];        // x fp16 hi
__device__ __half g_xl[(size_t)M_ * C_];        // x fp16 lo (residual)
__device__ __half g_w1[(size_t)N1_ * C_];       // Wqkv^T fp16 [6144,2048]
__device__ __half g_w2[(size_t)C_ * C_];        // Wproj^T fp16 [2048,2048]
// head-major Q/K/V (fp16), consumed by flash: [(b*H+h)*T + t]*D + d
__device__ __half g_qh2[(size_t)M_ * C_];       // Q hi (scaled)
__device__ __half g_ql2[(size_t)M_ * C_];       // Q lo
__device__ __half g_k1[(size_t)M_ * C_];        // K single fp16
__device__ __half g_vh2[(size_t)M_ * C_];       // V hi
__device__ __half g_vl2[(size_t)M_ * C_];       // V lo
// attention output fp16 hi/lo (token-major [t, C]), feeds proj GEMM
__device__ __half g_ah[(size_t)M_ * C_];
__device__ __half g_al[(size_t)M_ * C_];

// ---------------------------------------------------------------------------
// Helpers
// ---------------------------------------------------------------------------
__device__ __forceinline__ uint32_t smem_u32(const void* p) {
    uint32_t a;
    asm("{ .reg .u64 t; cvta.to.shared.u64 t, %1; cvt.u32.u64 %0, t; }"
        : "=r"(a) : "l"(p));
    return a;
}

#define LDSM_X4(r, a)                                                          \
    asm volatile("ldmatrix.sync.aligned.m8n8.x4.shared.b16 {%0,%1,%2,%3}, [%4];" \
        : "=r"((r)[0]), "=r"((r)[1]), "=r"((r)[2]), "=r"((r)[3]) : "r"(a))

#define LDSM_X4_T(r, a)                                                        \
    asm volatile("ldmatrix.sync.aligned.m8n8.x4.trans.shared.b16 {%0,%1,%2,%3}, [%4];" \
        : "=r"((r)[0]), "=r"((r)[1]), "=r"((r)[2]), "=r"((r)[3]) : "r"(a))

// fp16 MMA
#define MMA16816H(c, a, b0v, b1v)                                              \
    asm volatile("mma.sync.aligned.m16n8k16.row.col.f32.f16.f16.f32 "          \
        "{%0,%1,%2,%3}, {%4,%5,%6,%7}, {%8,%9}, {%0,%1,%2,%3};"                \
        : "+f"((c)[0]), "+f"((c)[1]), "+f"((c)[2]), "+f"((c)[3])               \
        : "r"((a)[0]), "r"((a)[1]), "r"((a)[2]), "r"((a)[3]),                  \
          "r"(b0v), "r"(b1v))

#define CP_ASYNC16(dst, src)                                                   \
    asm volatile("cp.async.cg.shared.global [%0], [%1], 16;"                   \
        :: "r"(dst), "l"(src))
#define CP_COMMIT()  asm volatile("cp.async.commit_group;" ::: "memory")
#define CP_WAIT1()   asm volatile("cp.async.wait_group 1;" ::: "memory")
#define CP_WAIT0()   asm volatile("cp.async.wait_group 0;" ::: "memory")

__device__ __forceinline__ uint32_t pack_h2(float a, float b) {
    __half2 t = __halves2half2(__float2half_rn(a), __float2half_rn(b));
    return *(uint32_t*)&t;
}

// fp16 split
__device__ __forceinline__ void split2h(float a, float b, uint32_t& h, uint32_t& l) {
    __half ha = __float2half_rn(a);
    __half hb = __float2half_rn(b);
    __half2 th = __halves2half2(ha, hb);
    h = *(uint32_t*)&th;
    __half2 tl = __halves2half2(__float2half_rn(a - __half2float(ha)),
                                __float2half_rn(b - __half2float(hb)));
    l = *(uint32_t*)&tl;
}

// ---------------------------------------------------------------------------
// Split fp32 -> fp16 hi/lo (for x)
// ---------------------------------------------------------------------------
__global__ void split_kernel_h(const float* __restrict__ in,
                               __half* __restrict__ hi,
                               __half* __restrict__ lo, int n4)
{
    int i = blockIdx.x * blockDim.x + threadIdx.x;
    if (i >= n4) return;
    float4 v = ((const float4*)in)[i];
    uint32_t h0, l0, h1, l1;
    split2h(v.x, v.y, h0, l0);
    split2h(v.z, v.w, h1, l1);
    uint32_t* H = (uint32_t*)hi;
    uint32_t* L = (uint32_t*)lo;
    H[2 * i] = h0; H[2 * i + 1] = h1;
    L[2 * i] = l0; L[2 * i + 1] = l1;
}

// ---------------------------------------------------------------------------
// Transpose: W[K,N] fp32 -> W^T fp16 [N,K]
// ---------------------------------------------------------------------------
__global__ __launch_bounds__(256)
void transpose_h_kernel(const float* __restrict__ W,
                        __half* __restrict__ hT, int K, int N)
{
    __shared__ float t[32][33];
    const int n0 = blockIdx.x * 32, k0 = blockIdx.y * 32;
    const int tx = threadIdx.x, ty = threadIdx.y;
#pragma unroll
    for (int j = 0; j < 4; j++)
        t[ty + j * 8][tx] = W[(size_t)(k0 + ty + j * 8) * N + n0 + tx];
    __syncthreads();
#pragma unroll
    for (int j = 0; j < 4; j++) {
        float v = t[tx][ty + j * 8];
        hT[(size_t)(n0 + ty + j * 8) * K + k0 + tx] = __float2half_rn(v);
    }
}

// ---------------------------------------------------------------------------
// fp16 2-pass GEMM: C = (Ah + Al) @ B^T + bias; 2 CTAs/SM, double-buffered.
// CTA tile 128x128, 8 warps of 64x32, K-chunk 32.
// Stage: Ah 8K | Al 8K | B 8K = 24K; 2 stages = 48K/CTA.
// MODE 0: fp32 out + bias (proj).
// MODE 1: QKV epilogue -> Q hi/lo fp16 (scaled), K single fp16, V hi/lo fp16.
// ---------------------------------------------------------------------------
#define GH_STAGE 24576u
#define GEMM_SMEM (2 * 24576)

#define SW64(row, segb) ((uint32_t)((row) * 64) + (((uint32_t)(segb)) ^ ((((uint32_t)(row) >> 1) & 3u) << 4)))

__device__ __forceinline__ void load_chunk_h(uint32_t sb, int buf,
                                             const __half* aH, const __half* aL,
                                             const __half* bB,
                                             int k0, int Kdim, int tid)
{
    const uint32_t st = sb + (uint32_t)buf * GH_STAGE;
    const __half* srcs[3] = { aH, aL, bB };
#pragma unroll
    for (int tl = 0; tl < 3; tl++) {
        const __half* s = srcs[tl] + k0;
        const uint32_t tb = st + (uint32_t)tl * 8192u;
#pragma unroll
        for (int l = 0; l < 2; l++) {
            int idx = tid + l * 256;          // 512 slots: 128 rows x 4 segs
            int row = idx >> 2, seg = idx & 3;
            CP_ASYNC16(tb + SW64(row, seg * 16),
                       s + (size_t)row * Kdim + seg * 8);
        }
    }
    CP_COMMIT();
}

template <int MODE>
__global__ __launch_bounds__(256, 2)
void mma_gemm(const __half* __restrict__ Ah, const __half* __restrict__ Al,
              const __half* __restrict__ Bm,
              const float* __restrict__ bias, float* __restrict__ Cm,
              __half* __restrict__ qh2, __half* __restrict__ ql2,
              __half* __restrict__ k1,
              __half* __restrict__ vh2, __half* __restrict__ vl2,
              int Ndim, int Kdim)
{
    extern __shared__ __align__(128) char smem[];
    const uint32_t sb = smem_u32(smem);
    const int tid  = threadIdx.x;
    const int wid  = tid >> 5;
    const int lane = tid & 31;
    const int wm   = wid & 1;
    const int wn   = wid >> 1;
    const int m0   = blockIdx.y * 128;
    const int n0   = blockIdx.x * 128;

    const __half* aH = Ah + (size_t)m0 * Kdim;
    const __half* aL = Al + (size_t)m0 * Kdim;
    const __half* bB = Bm + (size_t)n0 * Kdim;

    const int aRow = wm * 64 + (lane & 15);
    const uint32_t aKadd = (uint32_t)((lane >> 4) << 4);
    const int bRowB = wn * 32 + ((lane >> 4) & 1) * 8 + (lane & 7);
    const uint32_t bKadd = (uint32_t)(((lane >> 3) & 1) << 4);

    float c[4][4][4];
#pragma unroll
    for (int mi = 0; mi < 4; mi++)
#pragma unroll
        for (int ni = 0; ni < 4; ni++)
#pragma unroll
            for (int e = 0; e < 4; e++) c[mi][ni][e] = 0.f;

    const int nch = Kdim >> 5;
    load_chunk_h(sb, 0, aH, aL, bB, 0, Kdim, tid);

    for (int t = 0; t < nch; t++) {
        if (t + 1 < nch) {
            load_chunk_h(sb, (t + 1) & 1, aH, aL, bB, (t + 1) << 5, Kdim, tid);
            CP_WAIT1();
        } else {
            CP_WAIT0();
        }
        __syncthreads();

        const uint32_t st  = sb + (uint32_t)(t & 1) * GH_STAGE;
        const uint32_t tAh = st;
        const uint32_t tAl = st + 8192u;
        const uint32_t tB  = st + 16384u;

#pragma unroll
        for (int ks = 0; ks < 2; ks++) {
            uint32_t b4[2][4];
#pragma unroll
            for (int pr = 0; pr < 2; pr++) {
                const int br = bRowB + pr * 16;
                LDSM_X4(b4[pr], tB + SW64(br, ((uint32_t)(ks * 32) + bKadd)));
            }
#pragma unroll
            for (int mi = 0; mi < 4; mi++) {
                const int ar = aRow + mi * 16;
                const uint32_t aOff = SW64(ar, ((uint32_t)(ks * 32) + aKadd));
                uint32_t ah[4], al[4];
                LDSM_X4(ah, tAh + aOff);
                LDSM_X4(al, tAl + aOff);
                MMA16816H(c[mi][0], ah, b4[0][0], b4[0][1]);
                MMA16816H(c[mi][1], ah, b4[0][2], b4[0][3]);
                MMA16816H(c[mi][2], ah, b4[1][0], b4[1][1]);
                MMA16816H(c[mi][3], ah, b4[1][2], b4[1][3]);
                MMA16816H(c[mi][0], al, b4[0][0], b4[0][1]);
                MMA16816H(c[mi][1], al, b4[0][2], b4[0][3]);
                MMA16816H(c[mi][2], al, b4[1][0], b4[1][1]);
                MMA16816H(c[mi][3], al, b4[1][2], b4[1][3]);
            }
        }
        __syncthreads();
    }

    const int lr = lane >> 2;
    const int lc = (lane & 3) * 2;

    if (MODE == 0) {
#pragma unroll
        for (int mi = 0; mi < 4; mi++) {
            const int r0 = m0 + wm * 64 + mi * 16 + lr;
#pragma unroll
            for (int ni = 0; ni < 4; ni++) {
                const int col = n0 + wn * 32 + ni * 8 + lc;
                const float b0 = bias[col], b1 = bias[col + 1];
                float2 v0, v1;
                v0.x = c[mi][ni][0] + b0; v0.y = c[mi][ni][1] + b1;
                v1.x = c[mi][ni][2] + b0; v1.y = c[mi][ni][3] + b1;
                *(float2*)&Cm[(size_t)r0 * Ndim + col]       = v0;
                *(float2*)&Cm[(size_t)(r0 + 8) * Ndim + col] = v1;
            }
        }
    } else {
        // QKV epilogue: head-major [(b*H+h)*T + t]*D + d
        const int colbase = n0 + wn * 32;
        const int region  = colbase >> 11;          // 0=Q,1=K,2=V
        const int cr      = colbase & 2047;
        const int hh      = cr >> 7;
        const int dbase   = cr & 127;
#pragma unroll
        for (int mi = 0; mi < 4; mi++) {
            const int r0 = m0 + wm * 64 + mi * 16 + lr;
#pragma unroll
            for (int half = 0; half < 2; half++) {
                const int row = r0 + half * 8;
                const int bb  = row >> 11;
                const int tt  = row & 2047;
                const size_t base = (((size_t)(bb * H_ + hh)) * T_ + tt) * D_ + dbase;
#pragma unroll
                for (int ni = 0; ni < 4; ni++) {
                    const int col = colbase + ni * 8 + lc;
                    float v0 = c[mi][ni][2 * half]     + bias[col];
                    float v1 = c[mi][ni][2 * half + 1] + bias[col + 1];
                    const size_t off = base + ni * 8 + lc;
                    if (region == 1) {
                        *(uint32_t*)&k1[off] = pack_h2(v0, v1);
                    } else if (region == 0) {
                        uint32_t hv, lv;
                        split2h(v0 * SC_Q, v1 * SC_Q, hv, lv);
                        *(uint32_t*)&qh2[off] = hv;
                        *(uint32_t*)&ql2[off] = lv;
                    } else {
                        uint32_t hv, lv;
                        split2h(v0, v1, hv, lv);
                        *(uint32_t*)&vh2[off] = hv;
                        *(uint32_t*)&vl2[off] = lv;
                    }
                }
            }
        }
    }
}

// ---------------------------------------------------------------------------
// Flash attention (fp16, 2-pass products): 256 threads, BR=128, BC=64,
// register softmax, double-buffered cp.async KV pipeline.
// S = (Qh+Ql)@K^T (K single fp16); O += P@(Vh+Vl) (P single fp16).
// smem: Qhi 32K | Qlo 32K | 2 KV stages of (K 16K | Vhi 16K | Vlo 16K) = 160K.
// ---------------------------------------------------------------------------
#define FQ_HI 0u
#define FQ_LO 32768u
#define FKV0  65536u
#define FKV_STAGE 49152u
#define FL_SMEM 163840

__device__ __forceinline__ void flash_load_kv(uint32_t sb, uint32_t stage,
                                              const __half* k_g,
                                              const __half* vh_g,
                                              const __half* vl_g,
                                              int j0, int tid)
{
    const __half* srcs[3] = {
        k_g + (size_t)j0 * D_, vh_g + (size_t)j0 * D_, vl_g + (size_t)j0 * D_
    };
    // 3 tiles x 64 rows x 16 segs = 3072 slots; 256 threads x 12 iters
#pragma unroll
    for (int l = 0; l < 12; l++) {
        int idx  = tid + l * 256;
        int tile = idx >> 10;           // constant per unrolled l
        int rem  = idx & 1023;
        int row  = rem >> 4;
        int seg  = rem & 15;
        CP_ASYNC16(sb + stage + (uint32_t)(tile * 16384) +
                       (uint32_t)(row * 256 + ((seg * 16) ^ ((row & 7) << 4))),
                   srcs[tile] + (size_t)row * D_ + seg * 8);
    }
    CP_COMMIT();
}

__global__ __launch_bounds__(256, 1)
void flash_reg(const __half* __restrict__ qh2, const __half* __restrict__ ql2,
               const __half* __restrict__ k1,
               const __half* __restrict__ vh2, const __half* __restrict__ vl2,
               __half* __restrict__ ah_out, __half* __restrict__ al_out)
{
    extern __shared__ __align__(1024) char smf[];
    const uint32_t sb = smem_u32(smf);

    const int tid  = threadIdx.x;
    const int wid  = tid >> 5, lane = tid & 31;
    const int lr   = lane >> 2;
    const int lc   = (lane & 3) << 1;
    const int b    = blockIdx.x >> 4, h = blockIdx.x & 15;
    const int i0   = ((int)gridDim.y - 1 - (int)blockIdx.y) * 128;

    const size_t headoff = ((size_t)(b * H_ + h)) * T_ * D_;
    const __half* qh_g = qh2 + headoff + (size_t)i0 * D_;
    const __half* ql_g = ql2 + headoff + (size_t)i0 * D_;
    const __half* k_g  = k1  + headoff;
    const __half* vh_g = vh2 + headoff;
    const __half* vl_g = vl2 + headoff;

    {
        const __half* srcs[2] = { qh_g, ql_g };
#pragma unroll
        for (int l = 0; l < 16; l++) {
            int idx  = tid + l * 256;
            int tile = idx >> 11;
            int rem  = idx & 2047;
            int row  = rem >> 4;
            int seg  = rem & 15;
            CP_ASYNC16(sb + (uint32_t)(tile * 32768) +
                           (uint32_t)(row * 256 + ((seg * 16) ^ ((row & 7) << 4))),
                       srcs[tile] + (size_t)row * D_ + seg * 8);
        }
    }
    flash_load_kv(sb, FKV0, k_g, vh_g, vl_g, 0, tid);  // commits Q+kv0

    float o[16][4];
#pragma unroll
    for (int ni = 0; ni < 16; ni++)
#pragma unroll
        for (int e = 0; e < 4; e++) o[ni][e] = 0.f;
    float m0r = -1e30f, m1r = -1e30f, L0 = 0.f, L1 = 0.f;

    const uint32_t kxor  = (uint32_t)((lane & 7) << 4);
    const uint32_t aKadd = (uint32_t)((lane >> 4) << 4);
    const uint32_t qRow  = (uint32_t)((wid * 16 + (lane & 15)) * 256);
    const uint32_t kRowB = (uint32_t)((((lane >> 4) & 1) * 8 + (lane & 7)) * 256);
    const uint32_t bKadd = (uint32_t)(((lane >> 3) & 1) << 4);
    const uint32_t vRowB = (uint32_t)((lane & 15) * 256);
    const uint32_t vCadd = (uint32_t)(((lane >> 4) & 1) * 16);

    const int ntiles = i0 / 64 + 2;
    for (int jt = 0; jt < ntiles; jt++) {
        const int j0 = jt * 64;
        if (jt + 1 < ntiles) {
            flash_load_kv(sb, FKV0 + (uint32_t)((jt + 1) & 1) * FKV_STAGE,
                          k_g, vh_g, vl_g, (jt + 1) * 64, tid);
            CP_WAIT1();
        } else {
            CP_WAIT0();
        }
        __syncthreads();

        const uint32_t stg  = FKV0 + (uint32_t)(jt & 1) * FKV_STAGE;
        const uint32_t sK   = stg;
        const uint32_t sVhi = stg + 16384u;
        const uint32_t sVlo = stg + 32768u;

        // ---- S = (Qh+Ql) @ K^T : 128x64, 2 passes ----
        float s[8][4];
#pragma unroll
        for (int ni = 0; ni < 8; ni++)
#pragma unroll
            for (int e = 0; e < 4; e++) s[ni][e] = 0.f;

#pragma unroll
        for (int ks = 0; ks < 8; ks++) {
            const uint32_t ak = ((uint32_t)(ks * 32) + aKadd) ^ kxor;
            const uint32_t bk = ((uint32_t)(ks * 32) + bKadd) ^ kxor;
            uint32_t qh[4], ql[4];
            LDSM_X4(qh, sb + FQ_HI + qRow + ak);
            LDSM_X4(ql, sb + FQ_LO + qRow + ak);
#pragma unroll
            for (int n2 = 0; n2 < 4; n2++) {
                uint32_t k4[4];
                LDSM_X4(k4, sb + sK + kRowB + (uint32_t)(n2 * 4096) + bk);
                MMA16816H(s[2 * n2],     qh, k4[0], k4[1]);
                MMA16816H(s[2 * n2 + 1], qh, k4[2], k4[3]);
                MMA16816H(s[2 * n2],     ql, k4[0], k4[1]);
                MMA16816H(s[2 * n2 + 1], ql, k4[2], k4[3]);
            }
        }

        if (jt >= ntiles - 2) {
            const int r0 = i0 + wid * 16 + lr;
#pragma unroll
            for (int ni = 0; ni < 8; ni++) {
                int cc = j0 + ni * 8 + lc;
                if (cc     > r0)     s[ni][0] = -1e30f;
                if (cc + 1 > r0)     s[ni][1] = -1e30f;
                if (cc     > r0 + 8) s[ni][2] = -1e30f;
                if (cc + 1 > r0 + 8) s[ni][3] = -1e30f;
            }
        }

        float mx0 = -1e30f, mx1 = -1e30f;
#pragma unroll
        for (int ni = 0; ni < 8; ni++) {
            mx0 = fmaxf(mx0, fmaxf(s[ni][0], s[ni][1]));
            mx1 = fmaxf(mx1, fmaxf(s[ni][2], s[ni][3]));
        }
        mx0 = fmaxf(mx0, __shfl_xor_sync(0xffffffffu, mx0, 1));
        mx0 = fmaxf(mx0, __shfl_xor_sync(0xffffffffu, mx0, 2));
        mx1 = fmaxf(mx1, __shfl_xor_sync(0xffffffffu, mx1, 1));
        mx1 = fmaxf(mx1, __shfl_xor_sync(0xffffffffu, mx1, 2));
        const float mn0 = fmaxf(m0r, mx0);
        const float mn1 = fmaxf(m1r, mx1);
        const float co0 = exp2f(m0r - mn0);
        const float co1 = exp2f(m1r - mn1);
        m0r = mn0; m1r = mn1;

        float sum0 = 0.f, sum1 = 0.f;
#pragma unroll
        for (int ni = 0; ni < 8; ni++) {
            float e0 = exp2f(s[ni][0] - mn0);
            float e1 = exp2f(s[ni][1] - mn0);
            float e2 = exp2f(s[ni][2] - mn1);
            float e3 = exp2f(s[ni][3] - mn1);
            sum0 += e0 + e1; sum1 += e2 + e3;
            s[ni][0] = e0; s[ni][1] = e1; s[ni][2] = e2; s[ni][3] = e3;
        }
        sum0 += __shfl_xor_sync(0xffffffffu, sum0, 1);
        sum0 += __shfl_xor_sync(0xffffffffu, sum0, 2);
        sum1 += __shfl_xor_sync(0xffffffffu, sum1, 1);
        sum1 += __shfl_xor_sync(0xffffffffu, sum1, 2);
        L0 = L0 * co0 + sum0;
        L1 = L1 * co1 + sum1;

#pragma unroll
        for (int ni = 0; ni < 16; ni++) {
            o[ni][0] *= co0; o[ni][1] *= co0;
            o[ni][2] *= co1; o[ni][3] *= co1;
        }

        // ---- O += P @ (Vh + Vl), P single fp16 ----
#pragma unroll
        for (int kb = 0; kb < 4; kb++) {
            uint32_t ph[4];
            ph[0] = pack_h2(s[2 * kb][0],     s[2 * kb][1]);
            ph[1] = pack_h2(s[2 * kb][2],     s[2 * kb][3]);
            ph[2] = pack_h2(s[2 * kb + 1][0], s[2 * kb + 1][1]);
            ph[3] = pack_h2(s[2 * kb + 1][2], s[2 * kb + 1][3]);
            const uint32_t vrb = (uint32_t)(kb * 16 * 256) + vRowB;
#pragma unroll
            for (int n2 = 0; n2 < 8; n2++) {
                uint32_t vh4[4], vl4[4];
                const uint32_t cbo = (((uint32_t)(n2 * 32) + vCadd) ^ kxor);
                LDSM_X4_T(vh4, sb + sVhi + vrb + cbo);
                LDSM_X4_T(vl4, sb + sVlo + vrb + cbo);
                MMA16816H(o[2 * n2],     ph, vh4[0], vh4[1]);
                MMA16816H(o[2 * n2 + 1], ph, vh4[2], vh4[3]);
                MMA16816H(o[2 * n2],     ph, vl4[0], vl4[1]);
                MMA16816H(o[2 * n2 + 1], ph, vl4[2], vl4[3]);
            }
        }
        __syncthreads();
    }

    // ---- epilogue: normalize, split to fp16 hi/lo, token-major [t, C] ----
    {
        const float i0v = 1.f / L0;
        const float i1v = 1.f / L1;
        const size_t ra = (size_t)(b * T_ + i0 + wid * 16 + lr) * C_ + h * D_;
        const size_t rb = ra + (size_t)8 * C_;
#pragma unroll
        for (int ni = 0; ni < 16; ni++) {
            uint32_t hv, lv;
            split2h(o[ni][0] * i0v, o[ni][1] * i0v, hv, lv);
            *(uint32_t*)&ah_out[ra + ni * 8 + lc] = hv;
            *(uint32_t*)&al_out[ra + ni * 8 + lc] = lv;
            split2h(o[ni][2] * i1v, o[ni][3] * i1v, hv, lv);
            *(uint32_t*)&ah_out[rb + ni * 8 + lc] = hv;
            *(uint32_t*)&al_out[rb + ni * 8 + lc] = lv;
        }
    }
}

// ---------------------------------------------------------------------------
// Launch
// ---------------------------------------------------------------------------
extern "C" void kernel_launch(void* const* d_in, const int* in_sizes, int n_in,
                              void* d_out, int out_size)
{
    const float* x     = (const float*)d_in[0];
    const float* Wqkv  = (const float*)d_in[1];
    const float* bqkv  = (const float*)d_in[2];
    const float* Wproj = (const float*)d_in[3];
    const float* bproj = (const float*)d_in[4];
    float* out = (float*)d_out;

    __half *xh, *xl, *w1, *w2, *ah, *al;
    __half *qh2, *ql2, *k1, *vh2, *vl2;
    cudaGetSymbolAddress((void**)&xh,  g_xh);
    cudaGetSymbolAddress((void**)&xl,  g_xl);
    cudaGetSymbolAddress((void**)&w1,  g_w1);
    cudaGetSymbolAddress((void**)&w2,  g_w2);
    cudaGetSymbolAddress((void**)&ah,  g_ah);
    cudaGetSymbolAddress((void**)&al,  g_al);
    cudaGetSymbolAddress((void**)&qh2, g_qh2);
    cudaGetSymbolAddress((void**)&ql2, g_ql2);
    cudaGetSymbolAddress((void**)&k1,  g_k1);
    cudaGetSymbolAddress((void**)&vh2, g_vh2);
    cudaGetSymbolAddress((void**)&vl2, g_vl2);

    cudaFuncSetAttribute(mma_gemm<0>, cudaFuncAttributeMaxDynamicSharedMemorySize,
                         GEMM_SMEM);
    cudaFuncSetAttribute(mma_gemm<1>, cudaFuncAttributeMaxDynamicSharedMemorySize,
                         GEMM_SMEM);
    cudaFuncSetAttribute(flash_reg, cudaFuncAttributeMaxDynamicSharedMemorySize,
                         FL_SMEM);

    const int n4x = (M_ * C_) / 4;

    split_kernel_h<<<n4x / 256, 256>>>(x, xh, xl, n4x);
    transpose_h_kernel<<<dim3(N1_ / 32, C_ / 32), dim3(32, 8)>>>(Wqkv, w1, C_, N1_);
    transpose_h_kernel<<<dim3(C_ / 32, C_ / 32), dim3(32, 8)>>>(Wproj, w2, C_, C_);

    // 1) QKV GEMM (fp16 2-pass) -> Q hi/lo (scaled), K single, V hi/lo
    mma_gemm<1><<<dim3(N1_ / 128, M_ / 128), 256, GEMM_SMEM>>>(
        xh, xl, w1, bqkv, nullptr,
        qh2, ql2, k1, vh2, vl2, N1_, C_);

    // 2) causal flash attention (fp16 2-pass) -> fp16 hi/lo att
    flash_reg<<<dim3(B_ * H_, T_ / 128), 256, FL_SMEM>>>(
        qh2, ql2, k1, vh2, vl2, ah, al);

    // 3) proj GEMM (fp16 2-pass) -> fp32 out
    mma_gemm<0><<<dim3(C_ / 128, M_ / 128), 256, GEMM_SMEM>>>(
        ah, al, w2, bproj, out,
        nullptr, nullptr, nullptr, nullptr, nullptr, C_, C_);
}